// round 9
// baseline (speedup 1.0000x reference)
#include <cuda_runtime.h>
#include <math.h>
#include <stdint.h>

#define Tdim 2048
#define Ddim 256
#define CACT 64
#define CTIME 32
#define NROWS (8 * 2048)
#define LABEL_ID_ 3
#define OBSTR 98

// dynamic smem layout (gemm role), byte offsets
#define B_HI 0                  // 256 x 208B  ([k][96n bf16 + 8 pad])
#define B_LO 53248
#define A_HI 106496             // 128 x 256B  (one K-half, swizzled)
#define A_LO 139264
#define SMEM_BYTES 172032

__device__ float g_scr[(long)NROWS * 96];
__device__ int   g_done[8];

__device__ __forceinline__ float softplusf(float x) { return log1pf(expf(x)); }

__device__ __forceinline__ uint32_t smem_u32(const void* p) {
    uint32_t a;
    asm("{ .reg .u64 t; cvta.to.shared.u64 t, %1; cvt.u32.u64 %0, t; }" : "=r"(a) : "l"(p));
    return a;
}
// split x into bf16 hi + bf16 residual lo (packed pairs)
__device__ __forceinline__ void hilo2(float x0, float x1, uint32_t& hi, uint32_t& lo) {
    asm("cvt.rn.bf16x2.f32 %0, %1, %2;" : "=r"(hi) : "f"(x1), "f"(x0));
    float h0 = __uint_as_float(hi << 16);
    float h1 = __uint_as_float(hi & 0xffff0000u);
    asm("cvt.rn.bf16x2.f32 %0, %1, %2;" : "=r"(lo) : "f"(x1 - h1), "f"(x0 - h0));
}
__device__ __forceinline__ void ldsm4(uint32_t addr, uint32_t& r0, uint32_t& r1,
                                      uint32_t& r2, uint32_t& r3) {
    asm volatile("ldmatrix.sync.aligned.m8n8.x4.shared.b16 {%0,%1,%2,%3}, [%4];"
                 : "=r"(r0), "=r"(r1), "=r"(r2), "=r"(r3) : "r"(addr));
}
__device__ __forceinline__ void ldsm4t(uint32_t addr, uint32_t& r0, uint32_t& r1,
                                       uint32_t& r2, uint32_t& r3) {
    asm volatile("ldmatrix.sync.aligned.m8n8.x4.trans.shared.b16 {%0,%1,%2,%3}, [%4];"
                 : "=r"(r0), "=r"(r1), "=r"(r2), "=r"(r3) : "r"(addr));
}
__device__ __forceinline__ void mma16816(float* c, uint32_t a0, uint32_t a1,
                                         uint32_t a2, uint32_t a3,
                                         uint32_t b0, uint32_t b1) {
    asm volatile(
        "mma.sync.aligned.m16n8k16.row.col.f32.bf16.bf16.f32 "
        "{%0,%1,%2,%3},{%4,%5,%6,%7},{%8,%9},{%0,%1,%2,%3};"
        : "+f"(c[0]), "+f"(c[1]), "+f"(c[2]), "+f"(c[3])
        : "r"(a0), "r"(a1), "r"(a2), "r"(a3), "r"(b0), "r"(b1));
}

__global__ void reset_kernel() {
    if (threadIdx.x < 8) g_done[threadIdx.x] = 0;
}

__global__ void __launch_bounds__(512, 1) fat_kernel(
    const int* __restrict__ tokens, const float* __restrict__ h,
    const float* __restrict__ E,
    const float* __restrict__ Wn, const float* __restrict__ bn,
    const float* __restrict__ Wt, const float* __restrict__ bt,
    const float* __restrict__ tsa, const float* __restrict__ tst,
    const float* __restrict__ psa, const float* __restrict__ pst,
    const float* __restrict__ ppa, const float* __restrict__ ppt,
    const float* __restrict__ pta, const float* __restrict__ ptt,
    float* __restrict__ out)
{
    extern __shared__ char smc[];
    float* sm = (float*)smc;
    int tid = threadIdx.x, lane = tid & 31, wid = tid >> 5;
    int bx = blockIdx.x;

    if (bx >= 24) {
        // =============== GEMM role: HMMA bf16 hi/lo split ===============
        __shared__ float s_bias[96];
        __shared__ int s_lab[128];
        __shared__ int s_nlab;

        long rowbase = (long)(bx - 24) * 128;
        int b = (int)(rowbase >> 11);
        float s_ta = softplusf(*tsa), s_tt = softplusf(*tst);

        if (tid == 0) s_nlab = 0;
        if (tid < 96) s_bias[tid] = (tid < CACT) ? bn[tid] : bt[tid - CACT];

        uint32_t smem_base = smem_u32(smc);
        int rt = wid >> 1;          // row tile: rows [16rt, 16rt+16)
        int ch = wid & 1;           // col half: cols [48ch, 48ch+48)

        float acc[6][4];
#pragma unroll
        for (int j = 0; j < 6; ++j)
#pragma unroll
            for (int i = 0; i < 4; ++i) acc[j][i] = 0.f;

        // ---- stage B (folded weights, full K) as [k][n] hi/lo ----
        {
            const float2* E2 = (const float2*)E;
#pragma unroll
            for (int it = 0; it < 24; ++it) {
                int i = tid + 512 * it;           // 96*128 (c, k-pair)
                int c = i >> 7, kp = i & 127;
                const float2* wrow = (const float2*)((c < CACT) ? (Wn + c * Ddim)
                                                                : (Wt + (c - CACT) * Ddim));
                int erow = (c < CACT) ? (4 + c) : (68 + (c - CACT));
                float sc = (c < CACT) ? s_ta : s_tt;
                float2 wv = wrow[kp];
                float2 ev = E2[erow * 128 + kp];
                float x0 = fmaf(sc, ev.x, wv.x), x1 = fmaf(sc, ev.y, wv.y);
                uint32_t hi, lo;
                hilo2(x0, x1, hi, lo);
                int k = 2 * kp;
                *(unsigned short*)(smc + B_HI + k * 208 + c * 2)       = (unsigned short)(hi & 0xffff);
                *(unsigned short*)(smc + B_HI + (k + 1) * 208 + c * 2) = (unsigned short)(hi >> 16);
                *(unsigned short*)(smc + B_LO + k * 208 + c * 2)       = (unsigned short)(lo & 0xffff);
                *(unsigned short*)(smc + B_LO + (k + 1) * 208 + c * 2) = (unsigned short)(lo >> 16);
            }
        }

        const float4* gh4 = (const float4*)h;

        // lane-invariant parts of ldmatrix addresses
        int a_row = rt * 16 + (lane & 15);              // A tile row for this lane
        int a_half = lane >> 4;                          // k half (0/1) within chunk pair
        int b_kl = ((lane & 8) ? 8 : 0) + (lane & 7);    // k row within 16
        int b_ntsel = (lane < 16) ? 0 : 1;               // which ntile of the pair

        for (int s = 0; s < 2; ++s) {
            __syncthreads();
            // ---- stage A K-half: 128 rows x 16 chunks of 16B, swizzled ----
#pragma unroll
            for (int it = 0; it < 4; ++it) {
                int i = tid + 512 * it;          // 2048 slots
                int r = i >> 4, c = i & 15;
                float4 v0 = gh4[(rowbase + r) * 64 + s * 32 + 2 * c];
                float4 v1 = gh4[(rowbase + r) * 64 + s * 32 + 2 * c + 1];
                uint4 hi4, lo4;
                hilo2(v0.x, v0.y, hi4.x, lo4.x);
                hilo2(v0.z, v0.w, hi4.y, lo4.y);
                hilo2(v1.x, v1.y, hi4.z, lo4.z);
                hilo2(v1.z, v1.w, hi4.w, lo4.w);
                int sw = (c ^ (r & 7)) * 16;
                *(uint4*)(smc + A_HI + r * 256 + sw) = hi4;
                *(uint4*)(smc + A_LO + r * 256 + sw) = lo4;
            }
            __syncthreads();

#pragma unroll
            for (int kc = 0; kc < 8; ++kc) {
                // A fragments (hi & lo)
                int chunk = kc * 2 + a_half;
                uint32_t a_off = a_row * 256 + ((chunk ^ (a_row & 7)) * 16);
                uint32_t aH0, aH1, aH2, aH3, aL0, aL1, aL2, aL3;
                ldsm4(smem_base + A_HI + a_off, aH0, aH1, aH2, aH3);
                ldsm4(smem_base + A_LO + a_off, aL0, aL1, aL2, aL3);

                // B fragments: 3 x4.trans per set (6 n-tiles), hi & lo sets
                int k0 = s * 128 + kc * 16;
                uint32_t bH[12], bL[12];
#pragma unroll
                for (int j2 = 0; j2 < 3; ++j2) {
                    int nof = ch * 48 + j2 * 16 + b_ntsel * 8;
                    uint32_t b_off = (k0 + b_kl) * 208 + nof * 2;
                    ldsm4t(smem_base + B_HI + b_off,
                           bH[4 * j2 + 0], bH[4 * j2 + 1], bH[4 * j2 + 2], bH[4 * j2 + 3]);
                    ldsm4t(smem_base + B_LO + b_off,
                           bL[4 * j2 + 0], bL[4 * j2 + 1], bL[4 * j2 + 2], bL[4 * j2 + 3]);
                }
#pragma unroll
                for (int j = 0; j < 6; ++j) {
                    mma16816(acc[j], aH0, aH1, aH2, aH3, bH[2 * j], bH[2 * j + 1]);
                    mma16816(acc[j], aH0, aH1, aH2, aH3, bL[2 * j], bL[2 * j + 1]);
                    mma16816(acc[j], aL0, aL1, aL2, aL3, bH[2 * j], bH[2 * j + 1]);
                }
            }
        }

        // label rows of this tile
        if (tid < 128) {
            int tok = tokens[rowbase + tid];
            if (tok == LABEL_ID_) {
                int idx = atomicAdd(&s_nlab, 1);
                s_lab[idx] = tid;
            }
        }

        // ---- epilogue: fragments -> ob (reuse B region), bias add ----
        __syncthreads();
        float* ob = sm;
        {
            int r0 = rt * 16 + (lane >> 2);
            int cb = ch * 48 + 2 * (lane & 3);
#pragma unroll
            for (int j = 0; j < 6; ++j) {
                int col = cb + 8 * j;
                float2 v0 = make_float2(acc[j][0] + s_bias[col], acc[j][1] + s_bias[col + 1]);
                float2 v1 = make_float2(acc[j][2] + s_bias[col], acc[j][3] + s_bias[col + 1]);
                *(float2*)(ob + r0 * OBSTR + col) = v0;
                *(float2*)(ob + (r0 + 8) * OBSTR + col) = v1;
            }
        }
        // wait for proto blocks of this batch, merge proto sims
        if (tid == 0) {
            while (*(volatile int*)&g_done[b] < 3) __nanosleep(64);
        }
        __syncthreads();
        int nlab = s_nlab;
        for (int i = 0; i < nlab; ++i) {
            int r = s_lab[i];
            if (tid < 96)
                ob[r * OBSTR + tid] += __ldcg(&g_scr[(rowbase + r) * 96 + tid]);
        }
        __syncthreads();

        // coalesced stores
        float* outT = out + (long)NROWS * CACT;
#pragma unroll
        for (int k = 0; k < 8; ++k) {               // act: 4096 float2
            int i = tid + 512 * k;
            int r = i >> 5, c2 = i & 31;
            float2 v = *(float2*)(ob + r * OBSTR + 2 * c2);
            *(float2*)(out + (rowbase + r) * CACT + 2 * c2) = v;
        }
#pragma unroll
        for (int k = 0; k < 4; ++k) {               // time: 2048 float2
            int i = tid + 512 * k;
            int r = i >> 4, c2 = i & 15;
            float2 v = *(float2*)(ob + r * OBSTR + CACT + 2 * c2);
            *(float2*)(outT + (rowbase + r) * CTIME + 2 * c2) = v;
        }
    } else {
        // ====================== proto role (512 threads) ======================
        int b = bx / 3, part = bx % 3;
        int clo = (part == 0) ? 4 : (part == 1) ? 36 : 68;
        int klo = (part == 2) ? 68 : 4;
        int khi = (part == 2) ? 100 : 68;
        int cbase = part * 32;

        float* q    = sm;                    // 32 x 256
        float* hn   = q + 32 * Ddim;         // 256
        float* red  = hn + Ddim;             // 8
        float* n2   = red + 8;               // 32
        int*   ev_t = (int*)(n2 + 32);       // 2048
        int*   ev_n = ev_t + Tdim;           // 2048
        int*   toks = ev_n + Tdim;           // 2048
        __shared__ int s_nev;
        __shared__ float s_dq;

        for (int i = tid; i < Tdim; i += 512) toks[i] = tokens[(long)b * Tdim + i];
        __syncthreads();

        if (wid == 0) {
            int cnt = 0;
            for (int ch2 = 0; ch2 < Tdim / 32; ++ch2) {
                int t = ch2 * 32 + lane;
                bool isl = (toks[t] == LABEL_ID_);
                unsigned m = __ballot_sync(0xffffffffu, isl);
                if (isl) {
                    int idx = cnt + __popc(m & ((1u << lane) - 1u));
                    ev_t[idx] = t;
                    ev_n[idx] = toks[(t + 1) & (Tdim - 1)];
                }
                cnt += __popc(m);
            }
            if (lane == 0) s_nev = cnt;
        }

        float alpha = softplusf(part == 2 ? *ppt : *ppa);
        float scale = softplusf(part == 2 ? *pst : *psa) * softplusf(part == 2 ? *ptt : *pta);

        for (int c = wid; c < 32; c += 16) {
            const float* e = E + (long)(clo + c) * Ddim;
            float v[8]; float ss = 0.f;
#pragma unroll
            for (int k = 0; k < 8; ++k) { v[k] = e[lane + 32 * k]; ss += v[k] * v[k]; }
#pragma unroll
            for (int o = 16; o > 0; o >>= 1) ss += __shfl_xor_sync(0xffffffffu, ss, o);
            float inv = alpha / fmaxf(sqrtf(ss), 1e-12f);
#pragma unroll
            for (int k = 0; k < 8; ++k) q[c * Ddim + lane + 32 * k] = v[k] * inv;
        }
        if (tid < 32) n2[tid] = alpha * alpha;
        __syncthreads();

        int nev = s_nev;
        const float* hb = h + (long)b * Tdim * Ddim;
        int cnt = 0;
        float hv = (nev > 0 && tid < Ddim) ? hb[(long)ev_t[0] * Ddim + tid] : 0.f;

        for (int e = 0; e < nev; ++e) {
            int t = ev_t[e], ntok = ev_n[e];

            if (tid < Ddim) {
                float ss = hv * hv;
#pragma unroll
                for (int o = 16; o > 0; o >>= 1) ss += __shfl_xor_sync(0xffffffffu, ss, o);
                if (lane == 0) red[wid] = ss;
            }
            __syncthreads();
            float tot = red[0] + red[1] + red[2] + red[3]
                      + red[4] + red[5] + red[6] + red[7];
            float inv = 1.0f / fmaxf(sqrtf(tot), 1e-12f);
            float hn2 = tot * inv * inv;
            if (tid < Ddim) hn[tid] = hv * inv;
            __syncthreads();
            if (tid < Ddim && e + 1 < nev) hv = hb[(long)ev_t[e + 1] * Ddim + tid];

            bool supk = (ntok >= klo) && (ntok < khi);
            bool supm = (ntok >= clo) && (ntok < clo + 32);
            int cls = ntok - clo;

            int c = tid >> 4, seg = tid & 15;
            const float* qc = q + c * Ddim + seg * 16;
            const float* hc = hn + seg * 16;
            float s1 = 0.f;
#pragma unroll
            for (int i = 0; i < 16; ++i) {
                int dd = (i + seg) & 15;
                s1 += qc[dd] * hc[dd];
            }
#pragma unroll
            for (int o = 1; o < 16; o <<= 1) s1 += __shfl_xor_sync(0xffffffffu, s1, o);
            if (seg == 0) {
                if (supm && c == cls) s_dq = s1;
                float val = (cnt > 0) ? scale * s1 * rsqrtf(n2[c]) : 0.f;
                g_scr[((long)b * Tdim + t) * 96 + cbase + c] = val;
            }
            __syncthreads();

            if (supm) {
                if (tid < Ddim) q[cls * Ddim + tid] += hn[tid];
                if (tid == 0) n2[cls] += 2.f * s_dq + hn2;
            }
            if (supk) cnt++;
        }

        __syncthreads();
        if (tid == 0) {
            __threadfence();
            atomicAdd(&g_done[b], 1);
        }
    }
}

extern "C" void kernel_launch(void* const* d_in, const int* in_sizes, int n_in,
                              void* d_out, int out_size)
{
    cudaFuncSetAttribute(fat_kernel, cudaFuncAttributeMaxDynamicSharedMemorySize, SMEM_BYTES);

    reset_kernel<<<1, 32>>>();

    fat_kernel<<<152, 512, SMEM_BYTES>>>(
        (const int*)d_in[0], (const float*)d_in[1], (const float*)d_in[2],
        (const float*)d_in[3], (const float*)d_in[4],
        (const float*)d_in[5], (const float*)d_in[6],
        (const float*)d_in[7], (const float*)d_in[8],
        (const float*)d_in[9], (const float*)d_in[10],
        (const float*)d_in[11], (const float*)d_in[12],
        (const float*)d_in[13], (const float*)d_in[14],
        (float*)d_out);
}